// round 1
// baseline (speedup 1.0000x reference)
#include <cuda_runtime.h>
#include <math.h>

#define BATCH 4
#define LEN   4096
#define DIN   2048
#define NST   16
#define RNK   128
#define M_TOT (BATCH*LEN)   // 16384

// Scratch (device globals: no allocation allowed in kernel_launch)
__device__ float g_dt[(size_t)M_TOT * RNK];       // 8 MB
__device__ float g_B [(size_t)M_TOT * NST];       // 1 MB
__device__ float g_C [(size_t)M_TOT * NST];       // 1 MB
__device__ float g_delta[(size_t)M_TOT * DIN];    // 128 MB

// ---------------------------------------------------------------------------
// GEMM1: x_dbl[m, n] = sum_k X[m,k] * W[n,k],  M=16384, N=160, K=2048
// Output routed into g_dt (n<128), g_B (128..143), g_C (144..159).
// BM=64, BN=160 (full), BK=32. 256 threads. 8x5 outputs per thread.
// ---------------------------------------------------------------------------
__global__ __launch_bounds__(256) void gemm1_kernel(
    const float* __restrict__ X, const float* __restrict__ W)
{
    __shared__ float Xs[32][65];    // [k][m], padded
    __shared__ float Ws[32][161];   // [k][n], padded

    const int tid  = threadIdx.x;
    const int lane = tid & 31;
    const int grp  = tid >> 5;
    const int m0   = blockIdx.x * 64;

    float acc[8][5];
#pragma unroll
    for (int i = 0; i < 8; i++)
#pragma unroll
        for (int j = 0; j < 5; j++) acc[i][j] = 0.f;

    for (int k0 = 0; k0 < DIN; k0 += 32) {
        __syncthreads();
        // X tile: 64 rows x 32 k = 2048 floats -> 2 float4 per thread
#pragma unroll
        for (int q = 0; q < 2; q++) {
            int id  = q * 256 + tid;
            int row = id >> 3;
            int kc  = (id & 7) * 4;
            float4 v = *(const float4*)(X + (size_t)(m0 + row) * DIN + k0 + kc);
            Xs[kc + 0][row] = v.x; Xs[kc + 1][row] = v.y;
            Xs[kc + 2][row] = v.z; Xs[kc + 3][row] = v.w;
        }
        // W tile: 160 rows x 32 k = 5120 floats -> 5 float4 per thread
#pragma unroll
        for (int q = 0; q < 5; q++) {
            int id   = q * 256 + tid;
            int nrow = id >> 3;
            int kc   = (id & 7) * 4;
            float4 v = *(const float4*)(W + (size_t)nrow * DIN + k0 + kc);
            Ws[kc + 0][nrow] = v.x; Ws[kc + 1][nrow] = v.y;
            Ws[kc + 2][nrow] = v.z; Ws[kc + 3][nrow] = v.w;
        }
        __syncthreads();
#pragma unroll
        for (int kk = 0; kk < 32; kk++) {
            float xr[8], wv[5];
#pragma unroll
            for (int i = 0; i < 8; i++) xr[i] = Xs[kk][grp * 8 + i];
#pragma unroll
            for (int j = 0; j < 5; j++) wv[j] = Ws[kk][lane + 32 * j];
#pragma unroll
            for (int i = 0; i < 8; i++)
#pragma unroll
                for (int j = 0; j < 5; j++)
                    acc[i][j] = fmaf(xr[i], wv[j], acc[i][j]);
        }
    }

#pragma unroll
    for (int i = 0; i < 8; i++) {
        const int m = m0 + grp * 8 + i;
#pragma unroll
        for (int j = 0; j < 5; j++) {
            const int c = lane + 32 * j;
            const float v = acc[i][j];
            if (c < RNK)            g_dt[(size_t)m * RNK + c]            = v;
            else if (c < RNK + NST) g_B [(size_t)m * NST + (c - RNK)]    = v;
            else                    g_C [(size_t)m * NST + (c - RNK - NST)] = v;
        }
    }
}

// ---------------------------------------------------------------------------
// GEMM2: delta[m,d] = softplus( sum_r dt[m,r] * Wd[d,r] + bias[d] )
// M=16384, N=2048, K=128. BM=64, BN=128, BK=32. 8x4 outputs per thread.
// ---------------------------------------------------------------------------
__global__ __launch_bounds__(256) void gemm2_kernel(
    const float* __restrict__ Wd, const float* __restrict__ bias)
{
    __shared__ float Ts[32][65];    // dt tile [k][m]
    __shared__ float Ws[32][129];   // Wd tile [k][n]

    const int tid  = threadIdx.x;
    const int lane = tid & 31;
    const int grp  = tid >> 5;
    const int m0   = (blockIdx.x & 255) * 64;   // 256 m-tiles
    const int d0   = (blockIdx.x >> 8) * 128;   // 16 d-tiles

    float acc[8][4];
#pragma unroll
    for (int i = 0; i < 8; i++)
#pragma unroll
        for (int j = 0; j < 4; j++) acc[i][j] = 0.f;

    for (int k0 = 0; k0 < RNK; k0 += 32) {
        __syncthreads();
        // dt tile: 64 x 32 -> 2 float4 per thread
#pragma unroll
        for (int q = 0; q < 2; q++) {
            int id  = q * 256 + tid;
            int row = id >> 3;
            int kc  = (id & 7) * 4;
            float4 v = *(const float4*)(g_dt + (size_t)(m0 + row) * RNK + k0 + kc);
            Ts[kc + 0][row] = v.x; Ts[kc + 1][row] = v.y;
            Ts[kc + 2][row] = v.z; Ts[kc + 3][row] = v.w;
        }
        // Wd tile: 128 x 32 -> 4 float4 per thread
#pragma unroll
        for (int q = 0; q < 4; q++) {
            int id   = q * 256 + tid;
            int nrow = id >> 3;
            int kc   = (id & 7) * 4;
            float4 v = *(const float4*)(Wd + (size_t)(d0 + nrow) * RNK + k0 + kc);
            Ws[kc + 0][nrow] = v.x; Ws[kc + 1][nrow] = v.y;
            Ws[kc + 2][nrow] = v.z; Ws[kc + 3][nrow] = v.w;
        }
        __syncthreads();
#pragma unroll
        for (int kk = 0; kk < 32; kk++) {
            float xr[8], wv[4];
#pragma unroll
            for (int i = 0; i < 8; i++) xr[i] = Ts[kk][grp * 8 + i];
#pragma unroll
            for (int j = 0; j < 4; j++) wv[j] = Ws[kk][lane + 32 * j];
#pragma unroll
            for (int i = 0; i < 8; i++)
#pragma unroll
                for (int j = 0; j < 4; j++)
                    acc[i][j] = fmaf(xr[i], wv[j], acc[i][j]);
        }
    }

#pragma unroll
    for (int i = 0; i < 8; i++) {
        const int m = m0 + grp * 8 + i;
#pragma unroll
        for (int j = 0; j < 4; j++) {
            const int d = d0 + lane + 32 * j;
            float z  = acc[i][j] + bias[d];
            float sp = (z > 20.f) ? z : log1pf(__expf(z));
            g_delta[(size_t)m * DIN + d] = sp;
        }
    }
}

// ---------------------------------------------------------------------------
// Scan: 8 threads per (b,d) channel, 2 states each (N=16).
// h[n] = exp(delta*A[n]) * h[n] + delta*x*B[n];  y = sum_n h[n]*C[n] + D*x
// 65536 threads total. Depth-1 software prefetch of next timestep.
// ---------------------------------------------------------------------------
__global__ __launch_bounds__(256) void scan_kernel(
    const float* __restrict__ x, const float* __restrict__ A_log,
    const float* __restrict__ Dpar, float* __restrict__ out)
{
    const int tid = threadIdx.x;
    const int ch  = tid >> 3;            // 0..31 channels per block
    const int ng  = tid & 7;             // state pair index (2 states)
    const int b   = blockIdx.x >> 6;     // 4 batches
    const int d   = ((blockIdx.x & 63) << 5) + ch;

    const float2 al = *(const float2*)(A_log + (size_t)d * NST + ng * 2);
    const float A0 = -__expf(al.x);
    const float A1 = -__expf(al.y);
    const float Dd = Dpar[d];

    const float* xp = x       + (size_t)b * LEN * DIN + d;
    const float* dp = g_delta + (size_t)b * LEN * DIN + d;
    const float* Bp = g_B     + (size_t)b * LEN * NST + ng * 2;
    const float* Cp = g_C     + (size_t)b * LEN * NST + ng * 2;
    float*       op = out     + (size_t)b * LEN * DIN + d;

    float h0 = 0.f, h1 = 0.f;

    float  xt  = *xp;
    float  dtv = *dp;
    float2 Bt  = *(const float2*)Bp;
    float2 Ct  = *(const float2*)Cp;

    for (int l = 0; l < LEN; l++) {
        xp += DIN; dp += DIN; Bp += NST; Cp += NST;
        float xn = 0.f, dn = 0.f;
        float2 Bn = make_float2(0.f, 0.f), Cn = make_float2(0.f, 0.f);
        if (l < LEN - 1) {
            xn = *xp; dn = *dp;
            Bn = *(const float2*)Bp;
            Cn = *(const float2*)Cp;
        }

        const float e0 = __expf(dtv * A0);
        const float e1 = __expf(dtv * A1);
        const float s  = dtv * xt;
        h0 = fmaf(e0, h0, s * Bt.x);
        h1 = fmaf(e1, h1, s * Bt.y);
        float y = fmaf(h0, Ct.x, h1 * Ct.y);
        y += __shfl_xor_sync(0xffffffffu, y, 1);
        y += __shfl_xor_sync(0xffffffffu, y, 2);
        y += __shfl_xor_sync(0xffffffffu, y, 4);
        if (ng == 0) *op = fmaf(Dd, xt, y);
        op += DIN;

        xt = xn; dtv = dn; Bt = Bn; Ct = Cn;
    }
}

// ---------------------------------------------------------------------------
// Launch
// ---------------------------------------------------------------------------
extern "C" void kernel_launch(void* const* d_in, const int* in_sizes, int n_in,
                              void* d_out, int out_size)
{
    const float* x         = (const float*)d_in[0];
    const float* A_log     = (const float*)d_in[1];
    const float* D_param   = (const float*)d_in[2];
    const float* x_proj_w  = (const float*)d_in[3];
    const float* dt_proj_w = (const float*)d_in[4];
    const float* dt_proj_b = (const float*)d_in[5];
    float* out = (float*)d_out;

    gemm1_kernel<<<M_TOT / 64, 256>>>(x, x_proj_w);
    gemm2_kernel<<<(M_TOT / 64) * (DIN / 128), 256>>>(dt_proj_w, dt_proj_b);
    scan_kernel<<<BATCH * (DIN / 32), 256>>>(x, A_log, D_param, out);
}

// round 2
// speedup vs baseline: 1.6174x; 1.6174x over previous
#include <cuda_runtime.h>
#include <math.h>

#define BATCH 4
#define LEN   4096
#define DIN   2048
#define NST   16
#define RNK   128
#define M_TOT (BATCH*LEN)   // 16384
#define CHUNK 8

// Scratch (device globals: no allocation allowed in kernel_launch)
__device__ float g_dt[(size_t)M_TOT * RNK];       // 8 MB
__device__ float g_B [(size_t)M_TOT * NST];       // 1 MB
__device__ float g_C [(size_t)M_TOT * NST];       // 1 MB
__device__ float g_delta[(size_t)M_TOT * DIN];    // 128 MB

// ---------------------------------------------------------------------------
// GEMM1: x_dbl[m, n] = sum_k X[m,k] * W[n,k],  M=16384, N=160, K=2048
// ---------------------------------------------------------------------------
__global__ __launch_bounds__(256) void gemm1_kernel(
    const float* __restrict__ X, const float* __restrict__ W)
{
    __shared__ float Xs[32][65];    // [k][m], padded
    __shared__ float Ws[32][161];   // [k][n], padded

    const int tid  = threadIdx.x;
    const int lane = tid & 31;
    const int grp  = tid >> 5;
    const int m0   = blockIdx.x * 64;

    float acc[8][5];
#pragma unroll
    for (int i = 0; i < 8; i++)
#pragma unroll
        for (int j = 0; j < 5; j++) acc[i][j] = 0.f;

    for (int k0 = 0; k0 < DIN; k0 += 32) {
        __syncthreads();
#pragma unroll
        for (int q = 0; q < 2; q++) {
            int id  = q * 256 + tid;
            int row = id >> 3;
            int kc  = (id & 7) * 4;
            float4 v = *(const float4*)(X + (size_t)(m0 + row) * DIN + k0 + kc);
            Xs[kc + 0][row] = v.x; Xs[kc + 1][row] = v.y;
            Xs[kc + 2][row] = v.z; Xs[kc + 3][row] = v.w;
        }
#pragma unroll
        for (int q = 0; q < 5; q++) {
            int id   = q * 256 + tid;
            int nrow = id >> 3;
            int kc   = (id & 7) * 4;
            float4 v = *(const float4*)(W + (size_t)nrow * DIN + k0 + kc);
            Ws[kc + 0][nrow] = v.x; Ws[kc + 1][nrow] = v.y;
            Ws[kc + 2][nrow] = v.z; Ws[kc + 3][nrow] = v.w;
        }
        __syncthreads();
#pragma unroll
        for (int kk = 0; kk < 32; kk++) {
            float xr[8], wv[5];
#pragma unroll
            for (int i = 0; i < 8; i++) xr[i] = Xs[kk][grp * 8 + i];
#pragma unroll
            for (int j = 0; j < 5; j++) wv[j] = Ws[kk][lane + 32 * j];
#pragma unroll
            for (int i = 0; i < 8; i++)
#pragma unroll
                for (int j = 0; j < 5; j++)
                    acc[i][j] = fmaf(xr[i], wv[j], acc[i][j]);
        }
    }

#pragma unroll
    for (int i = 0; i < 8; i++) {
        const int m = m0 + grp * 8 + i;
#pragma unroll
        for (int j = 0; j < 5; j++) {
            const int c = lane + 32 * j;
            const float v = acc[i][j];
            if (c < RNK)            g_dt[(size_t)m * RNK + c]            = v;
            else if (c < RNK + NST) g_B [(size_t)m * NST + (c - RNK)]    = v;
            else                    g_C [(size_t)m * NST + (c - RNK - NST)] = v;
        }
    }
}

// ---------------------------------------------------------------------------
// GEMM2: delta[m,d] = softplus( sum_r dt[m,r] * Wd[d,r] + bias[d] )
// ---------------------------------------------------------------------------
__global__ __launch_bounds__(256) void gemm2_kernel(
    const float* __restrict__ Wd, const float* __restrict__ bias)
{
    __shared__ float Ts[32][65];
    __shared__ float Ws[32][129];

    const int tid  = threadIdx.x;
    const int lane = tid & 31;
    const int grp  = tid >> 5;
    const int m0   = (blockIdx.x & 255) * 64;
    const int d0   = (blockIdx.x >> 8) * 128;

    float acc[8][4];
#pragma unroll
    for (int i = 0; i < 8; i++)
#pragma unroll
        for (int j = 0; j < 4; j++) acc[i][j] = 0.f;

    for (int k0 = 0; k0 < RNK; k0 += 32) {
        __syncthreads();
#pragma unroll
        for (int q = 0; q < 2; q++) {
            int id  = q * 256 + tid;
            int row = id >> 3;
            int kc  = (id & 7) * 4;
            float4 v = *(const float4*)(g_dt + (size_t)(m0 + row) * RNK + k0 + kc);
            Ts[kc + 0][row] = v.x; Ts[kc + 1][row] = v.y;
            Ts[kc + 2][row] = v.z; Ts[kc + 3][row] = v.w;
        }
#pragma unroll
        for (int q = 0; q < 4; q++) {
            int id   = q * 256 + tid;
            int nrow = id >> 3;
            int kc   = (id & 7) * 4;
            float4 v = *(const float4*)(Wd + (size_t)(d0 + nrow) * RNK + k0 + kc);
            Ws[kc + 0][nrow] = v.x; Ws[kc + 1][nrow] = v.y;
            Ws[kc + 2][nrow] = v.z; Ws[kc + 3][nrow] = v.w;
        }
        __syncthreads();
#pragma unroll
        for (int kk = 0; kk < 32; kk++) {
            float xr[8], wv[4];
#pragma unroll
            for (int i = 0; i < 8; i++) xr[i] = Ts[kk][grp * 8 + i];
#pragma unroll
            for (int j = 0; j < 4; j++) wv[j] = Ws[kk][lane + 32 * j];
#pragma unroll
            for (int i = 0; i < 8; i++)
#pragma unroll
                for (int j = 0; j < 4; j++)
                    acc[i][j] = fmaf(xr[i], wv[j], acc[i][j]);
        }
    }

#pragma unroll
    for (int i = 0; i < 8; i++) {
        const int m = m0 + grp * 8 + i;
#pragma unroll
        for (int j = 0; j < 4; j++) {
            const int d = d0 + lane + 32 * j;
            float z  = acc[i][j] + bias[d];
            float sp = (z > 20.f) ? z : log1pf(__expf(z));
            g_delta[(size_t)m * DIN + d] = sp;
        }
    }
}

// ---------------------------------------------------------------------------
// Scan v2: 8 threads per (b,d) channel, 2 states each. CHUNK=8 timesteps
// staged into registers per iteration (32 independent LDGs -> MLP ~32),
// then 8 recurrence steps from registers. One DRAM latency per 8 steps.
// ---------------------------------------------------------------------------
__global__ __launch_bounds__(256) void scan_kernel(
    const float* __restrict__ x, const float* __restrict__ A_log,
    const float* __restrict__ Dpar, float* __restrict__ out)
{
    const int tid = threadIdx.x;
    const int ch  = tid >> 3;            // 0..31 channels per block
    const int ng  = tid & 7;             // state-pair index
    const int b   = blockIdx.x >> 6;     // 4 batches
    const int d   = ((blockIdx.x & 63) << 5) + ch;

    const float2 al = *(const float2*)(A_log + (size_t)d * NST + ng * 2);
    const float A0 = -__expf(al.x);
    const float A1 = -__expf(al.y);
    const float Dd = Dpar[d];

    const float* xp = x       + (size_t)b * LEN * DIN + d;
    const float* dp = g_delta + (size_t)b * LEN * DIN + d;
    const float* Bp = g_B     + (size_t)b * LEN * NST + ng * 2;
    const float* Cp = g_C     + (size_t)b * LEN * NST + ng * 2;
    float*       op = out     + (size_t)b * LEN * DIN + d;

    float h0 = 0.f, h1 = 0.f;

    for (int c = 0; c < LEN / CHUNK; c++) {
        float  xs[CHUNK], ds[CHUNK];
        float2 Bs[CHUNK], Cs[CHUNK];
#pragma unroll
        for (int j = 0; j < CHUNK; j++) {
            xs[j] = xp[(size_t)j * DIN];
            ds[j] = dp[(size_t)j * DIN];
            Bs[j] = *(const float2*)(Bp + j * NST);
            Cs[j] = *(const float2*)(Cp + j * NST);
        }
        xp += (size_t)CHUNK * DIN;
        dp += (size_t)CHUNK * DIN;
        Bp += CHUNK * NST;
        Cp += CHUNK * NST;

#pragma unroll
        for (int j = 0; j < CHUNK; j++) {
            const float e0 = __expf(ds[j] * A0);
            const float e1 = __expf(ds[j] * A1);
            const float s  = ds[j] * xs[j];
            h0 = fmaf(e0, h0, s * Bs[j].x);
            h1 = fmaf(e1, h1, s * Bs[j].y);
            float y = fmaf(h0, Cs[j].x, h1 * Cs[j].y);
            y += __shfl_xor_sync(0xffffffffu, y, 1);
            y += __shfl_xor_sync(0xffffffffu, y, 2);
            y += __shfl_xor_sync(0xffffffffu, y, 4);
            if (ng == 0) op[(size_t)j * DIN] = fmaf(Dd, xs[j], y);
        }
        op += (size_t)CHUNK * DIN;
    }
}

// ---------------------------------------------------------------------------
// Launch
// ---------------------------------------------------------------------------
extern "C" void kernel_launch(void* const* d_in, const int* in_sizes, int n_in,
                              void* d_out, int out_size)
{
    const float* x         = (const float*)d_in[0];
    const float* A_log     = (const float*)d_in[1];
    const float* D_param   = (const float*)d_in[2];
    const float* x_proj_w  = (const float*)d_in[3];
    const float* dt_proj_w = (const float*)d_in[4];
    const float* dt_proj_b = (const float*)d_in[5];
    float* out = (float*)d_out;

    gemm1_kernel<<<M_TOT / 64, 256>>>(x, x_proj_w);
    gemm2_kernel<<<(M_TOT / 64) * (DIN / 128), 256>>>(dt_proj_w, dt_proj_b);
    scan_kernel<<<BATCH * (DIN / 32), 256>>>(x, A_log, D_param, out);
}